// round 11
// baseline (speedup 1.0000x reference)
#include <cuda_runtime.h>

// Shape (N,C,T,V,M) = (256,3,600,25,2), f32
// Thread map: joint c = tid%25 (fixed), row strip g = tid/25 -> rows [90g, 90g+90).
// Temporal neighbor = next iteration's register -> only 2 LDG/iter (x and y).
#define NB      256
#define TT      600
#define VV      25
#define GROUPS  20                 // 500 / 25
#define RPG     90                 // rows per group (1800 / 20)
#define F2_N    45000              // float2 per sample
#define THREADS 500
#define NTOT    23040000.0f

__device__ float        g_partial[NB];
__device__ unsigned int g_count;   // zero at load; finalizer rearms each replay

__global__ __launch_bounds__(THREADS, 2)
void loss_strip(const float2* __restrict__ x, const float2* __restrict__ y,
                float* __restrict__ out)
{
    const int n   = blockIdx.x;
    const int tid = threadIdx.x;
    const int c   = tid % VV;          // fixed joint
    const int g   = tid / VV;          // row-strip id (0..19)

    // float2 index of (row = 90g, joint c) within sample n
    const size_t base = (size_t)n * F2_N + (size_t)g * (RPG * VV) + c;
    const float2* __restrict__ xp = x + base;
    const float2* __restrict__ yp = y + base;

    __shared__ float sAbs[VV];
    __shared__ float sSq[VV];
    __shared__ bool  sLast;
    if (tid < VV) { sAbs[tid] = 0.0f; sSq[tid] = 0.0f; }
    __syncthreads();

    float accA = 0.0f;                 // sum |x[t+1]-x[t]| (register-carried neighbor)
    float accS = 0.0f;                 // sum (x-y)^2

    float2 a = __ldg(&xp[0]);          // row 90g

    // Channel boundary (t==599) inside the strip: (g,j) in {(6,59),(13,29)};
    // (19,89) is the tensor edge, handled by the guarded tail.
    #pragma unroll 6
    for (int j = 0; j < RPG - 1; ++j) {
        const int idx = VV * j;                    // 25 float2 per row
        const float2 an = __ldg(&xp[idx + VV]);    // row 90g + j + 1
        const float2 yv = __ldg(&yp[idx]);

        const float dx = a.x - yv.x;
        const float dy = a.y - yv.y;
        accS = fmaf(dx, dx, accS);
        accS = fmaf(dy, dy, accS);

        const bool skip = (j == 59 && g == 6) || (j == 29 && g == 13);
        if (!skip)
            accA += fabsf(an.x - a.x) + fabsf(an.y - a.y);

        a = an;
    }

    // j = 89: last row of the strip
    {
        const int idx = VV * (RPG - 1);
        const float2 yv = __ldg(&yp[idx]);
        const float dx = a.x - yv.x;
        const float dy = a.y - yv.y;
        accS = fmaf(dx, dx, accS);
        accS = fmaf(dy, dy, accS);

        if (g < GROUPS - 1) {                      // neighbor row 90(g+1); g=19 is t=599
            const float2 an = __ldg(&xp[idx + VV]);
            accA += fabsf(an.x - a.x) + fabsf(an.y - a.y);
        }
    }

    atomicAdd(&sAbs[c], accA);     // 20 threads per joint slot; tail-time only
    atomicAdd(&sSq[c],  accS);
    __syncthreads();

    // Warp 0: per-sample combine, publish partial, elect last block
    if (tid < 32) {
        float myAbs = (tid < VV) ? sAbs[tid] : 0.0f;
        float mySq  = (tid < VV) ? sSq[tid]  : 0.0f;

        float tot = myAbs;
        #pragma unroll
        for (int o = 16; o > 0; o >>= 1)
            tot += __shfl_xor_sync(0xffffffffu, tot, o);

        float contrib = myAbs * mySq;
        #pragma unroll
        for (int o = 16; o > 0; o >>= 1)
            contrib += __shfl_xor_sync(0xffffffffu, contrib, o);

        if (tid == 0) {
            g_partial[n] = (float)VV * contrib / tot;
            __threadfence();
            unsigned int prev = atomicAdd(&g_count, 1u);
            sLast = (prev == NB - 1);
        }
    }
    __syncthreads();

    // Last-arriving block: reduce all 256 partials (fixed order -> deterministic)
    if (sLast && tid < 32) {
        __threadfence();
        float val = 0.0f;
        #pragma unroll
        for (int k = 0; k < NB / 32; ++k)
            val += __ldcg(&g_partial[tid + k * 32]);
        #pragma unroll
        for (int o = 16; o > 0; o >>= 1)
            val += __shfl_xor_sync(0xffffffffu, val, o);
        if (tid == 0) {
            out[0]  = val / NTOT;
            g_count = 0u;              // rearm for next graph replay
            __threadfence();
        }
    }
}

extern "C" void kernel_launch(void* const* d_in, const int* in_sizes, int n_in,
                              void* d_out, int out_size)
{
    (void)in_sizes; (void)n_in; (void)out_size;
    loss_strip<<<NB, THREADS>>>((const float2*)d_in[0],
                                (const float2*)d_in[1],
                                (float*)d_out);
}

// round 12
// speedup vs baseline: 1.3843x; 1.3843x over previous
#include <cuda_runtime.h>

// Shape (N,C,T,V,M) = (256,3,600,25,2), f32
#define NB      256
#define CC      3
#define TT      600
#define VV      25
#define ROWS    (CC * TT)          // 1800 rows of 50 floats per sample
#define F2_ROW  VV                 // 25 float2 per row (one float2 per joint)
#define F2_N    (ROWS * F2_ROW)    // 45000 float2 per sample
#define THREADS 500                // multiple of 25 -> fixed joint per thread
#define ROWS_IT (THREADS / VV)     // 20 rows per iteration
#define ITERS   (ROWS / ROWS_IT)   // 90 iterations
#define NTOT    23040000.0f

__device__ float        g_partial[NB];
__device__ unsigned int g_count;     // zero-init at module load; reset by last block

__global__ __launch_bounds__(THREADS, 2)
void loss_fused(const float2* __restrict__ x, const float2* __restrict__ y,
                float* __restrict__ out)
{
    const int n   = blockIdx.x;
    const int tid = threadIdx.x;
    const int v   = tid % VV;
    const int r0  = tid / VV;

    const float2* __restrict__ xn = x + (size_t)n * F2_N;
    const float2* __restrict__ yn = y + (size_t)n * F2_N;

    __shared__ float sAbs[VV];
    __shared__ float sSq[VV];
    __shared__ bool  sLast;
    if (tid < VV) { sAbs[tid] = 0.0f; sSq[tid] = 0.0f; }
    __syncthreads();

    float accA = 0.0f;   // sum |x[t+1]-x[t]|
    float accS = 0.0f;   // sum (x-y)^2

    #pragma unroll 6
    for (int j = 0; j < ITERS; ++j) {
        const int idx = tid + j * THREADS;
        const int row = r0  + j * ROWS_IT;
        const int t   = row % TT;

        const float2 a  = __ldg(&xn[idx]);
        const float2 yv = __ldcs(&yn[idx]);     // read-once stream: evict-first
        const float dx = a.x - yv.x;
        const float dy = a.y - yv.y;
        accS = fmaf(dx, dx, accS);
        accS = fmaf(dy, dy, accS);

        if (t != TT - 1) {                       // diff stays within channel c
            const float2 b = __ldg(&xn[idx + F2_ROW]);
            accA += fabsf(b.x - a.x) + fabsf(b.y - a.y);
        }
    }

    atomicAdd(&sAbs[v], accA);
    atomicAdd(&sSq[v],  accS);
    __syncthreads();

    // Warp 0: per-sample combine, publish partial, elect last block
    if (tid < 32) {
        float myAbs = (tid < VV) ? sAbs[tid] : 0.0f;
        float mySq  = (tid < VV) ? sSq[tid]  : 0.0f;

        float tot = myAbs;
        #pragma unroll
        for (int o = 16; o > 0; o >>= 1)
            tot += __shfl_xor_sync(0xffffffffu, tot, o);

        float contrib = myAbs * mySq;
        #pragma unroll
        for (int o = 16; o > 0; o >>= 1)
            contrib += __shfl_xor_sync(0xffffffffu, contrib, o);

        if (tid == 0) {
            g_partial[n] = (float)VV * contrib / tot;
            __threadfence();
            unsigned int prev = atomicAdd(&g_count, 1u);
            sLast = (prev == NB - 1);
        }
    }
    __syncthreads();

    // Last-arriving block: reduce all 256 partials (fixed order -> deterministic)
    if (sLast && tid < 32) {
        __threadfence();
        float val = 0.0f;
        #pragma unroll
        for (int k = 0; k < NB / 32; ++k)
            val += g_partial[tid + k * 32];
        #pragma unroll
        for (int o = 16; o > 0; o >>= 1)
            val += __shfl_xor_sync(0xffffffffu, val, o);
        if (tid == 0) {
            out[0]  = val / NTOT;
            g_count = 0u;            // rearm for next graph replay
            __threadfence();
        }
    }
}

extern "C" void kernel_launch(void* const* d_in, const int* in_sizes, int n_in,
                              void* d_out, int out_size)
{
    (void)in_sizes; (void)n_in; (void)out_size;
    loss_fused<<<NB, THREADS>>>((const float2*)d_in[0],
                                (const float2*)d_in[1],
                                (float*)d_out);
}